// round 2
// baseline (speedup 1.0000x reference)
#include <cuda_runtime.h>
#include <cstdint>

#define N_ROWS 16384
#define H_DIM  512
#define D_DIM  256
#define K_CB   4096

// -------- scratch (static device arrays; no cudaMalloc allowed) --------
__device__ float              g_X[N_ROWS * D_DIM];   // post-LN activations u
__device__ float              g_a[N_ROWS];           // fl(sum u^2) per row
__device__ float              g_b[K_CB];             // fl(sum e^2) per code
__device__ unsigned long long g_best[N_ROWS];        // packed (~sortable(d) | ~k)

// ============================================================================
// Kernel 1: projection GEMM + bias + LayerNorm (fused).
// BM=64, BN=256 (full D so LN fuses), BK=32, 256 threads, 8x8 microtile.
// Per-thread fp32 FMA accumulation in ascending-k order.
// ============================================================================
__global__ __launch_bounds__(256) void proj_ln_kernel(
    const float* __restrict__ F,      // [N, H]
    const float* __restrict__ Wp,     // [D, H]
    const float* __restrict__ bp,     // [D]
    const float* __restrict__ gamma,  // [D]
    const float* __restrict__ beta)   // [D]
{
    __shared__ float As[32][68];    // [k][m], padded
    __shared__ float Bs[32][260];   // [k][d], padded

    const int tid  = threadIdx.x;
    const int warp = tid >> 5;      // rows warp*8..+8
    const int lane = tid & 31;      // cols lane*8..+8
    const int m0   = blockIdx.x * 64;

    float acc[8][8];
#pragma unroll
    for (int i = 0; i < 8; i++)
#pragma unroll
        for (int j = 0; j < 8; j++) acc[i][j] = 0.f;

    for (int k0 = 0; k0 < H_DIM; k0 += 32) {
#pragma unroll
        for (int r = 0; r < 2; r++) {
            int idx = tid + r * 256;          // 0..511
            int row = idx >> 3;
            int kk  = (idx & 7) * 4;
            float4 v = *reinterpret_cast<const float4*>(
                &F[(size_t)(m0 + row) * H_DIM + k0 + kk]);
            As[kk + 0][row] = v.x; As[kk + 1][row] = v.y;
            As[kk + 2][row] = v.z; As[kk + 3][row] = v.w;
        }
#pragma unroll
        for (int r = 0; r < 8; r++) {
            int idx = tid + r * 256;          // 0..2047
            int d  = idx >> 3;
            int kk = (idx & 7) * 4;
            float4 v = *reinterpret_cast<const float4*>(
                &Wp[(size_t)d * H_DIM + k0 + kk]);
            Bs[kk + 0][d] = v.x; Bs[kk + 1][d] = v.y;
            Bs[kk + 2][d] = v.z; Bs[kk + 3][d] = v.w;
        }
        __syncthreads();
#pragma unroll
        for (int k = 0; k < 32; k++) {
            float4 a0 = *reinterpret_cast<const float4*>(&As[k][warp * 8]);
            float4 a1 = *reinterpret_cast<const float4*>(&As[k][warp * 8 + 4]);
            float4 b0 = *reinterpret_cast<const float4*>(&Bs[k][lane * 8]);
            float4 b1 = *reinterpret_cast<const float4*>(&Bs[k][lane * 8 + 4]);
            float a[8] = {a0.x, a0.y, a0.z, a0.w, a1.x, a1.y, a1.z, a1.w};
            float b[8] = {b0.x, b0.y, b0.z, b0.w, b1.x, b1.y, b1.z, b1.w};
#pragma unroll
            for (int i = 0; i < 8; i++)
#pragma unroll
                for (int j = 0; j < 8; j++) acc[i][j] = fmaf(a[i], b[j], acc[i][j]);
        }
        __syncthreads();
    }

    // epilogue: +bp, LayerNorm over 256 cols of each row, write g_X
    float bpv[8], gv[8], bv[8];
#pragma unroll
    for (int j = 0; j < 8; j++) {
        int d = lane * 8 + j;
        bpv[j] = bp[d]; gv[j] = gamma[d]; bv[j] = beta[d];
    }
#pragma unroll
    for (int i = 0; i < 8; i++) {
#pragma unroll
        for (int j = 0; j < 8; j++) acc[i][j] += bpv[j];
        float s = 0.f;
#pragma unroll
        for (int j = 0; j < 8; j++) s += acc[i][j];
#pragma unroll
        for (int o = 16; o > 0; o >>= 1) s += __shfl_xor_sync(0xffffffffu, s, o);
        float mu = s * (1.f / 256.f);
        // two-pass variance like jnp.var: mean((x-mu)^2)
        float ss = 0.f;
#pragma unroll
        for (int j = 0; j < 8; j++) {
            float dlt = acc[i][j] - mu;
            ss += dlt * dlt;
        }
#pragma unroll
        for (int o = 16; o > 0; o >>= 1) ss += __shfl_xor_sync(0xffffffffu, ss, o);
        float var = ss * (1.f / 256.f);
        float rs  = rsqrtf(var + 1e-5f);
        int row = m0 + warp * 8 + i;
        float out[8];
#pragma unroll
        for (int j = 0; j < 8; j++)
            out[j] = (acc[i][j] - mu) * rs * gv[j] + bv[j];
        *reinterpret_cast<float4*>(&g_X[(size_t)row * D_DIM + lane * 8]) =
            make_float4(out[0], out[1], out[2], out[3]);
        *reinterpret_cast<float4*>(&g_X[(size_t)row * D_DIM + lane * 8 + 4]) =
            make_float4(out[4], out[5], out[6], out[7]);
    }
}

// ============================================================================
// Kernel 2: g_b[k] = fl-sequential sum of emb[k,d]^2 (square rounded, then add)
// One thread per codebook row — exact left-to-right fp32 order.
// ============================================================================
__global__ __launch_bounds__(256) void b_kernel(const float* __restrict__ emb)
{
    int k = blockIdx.x * blockDim.x + threadIdx.x;
    if (k >= K_CB) return;
    const float* row = emb + (size_t)k * D_DIM;
    float acc = 0.f;
#pragma unroll 8
    for (int d = 0; d < D_DIM; d++) {
        float v = row[d];
        acc = __fadd_rn(acc, __fmul_rn(v, v));
    }
    g_b[k] = acc;
}

// ============================================================================
// Kernel 3: g_a[m] = fl-sequential sum of u[m,d]^2; also init g_best.
// ============================================================================
__global__ __launch_bounds__(256) void a_kernel()
{
    int m = blockIdx.x * blockDim.x + threadIdx.x;
    if (m >= N_ROWS) return;
    const float* row = g_X + (size_t)m * D_DIM;
    float acc = 0.f;
#pragma unroll 8
    for (int d = 0; d < D_DIM; d++) {
        float v = row[d];
        acc = __fadd_rn(acc, __fmul_rn(v, v));
    }
    g_a[m] = acc;
    g_best[m] = 0ull;
}

// ============================================================================
// Kernel 4: score GEMM + fused per-row argmin of reference-rounded distance.
//   dot  = fp32 FMA sum over d (ascending)
//   c    = fl(2 * dot)
//   d    = fl( fl(a_m + b_k) - c )          <- exact reference op sequence
//   argmin d over k, first (smallest) index wins ties.
// Packed for atomicMax: ((~sortable_asc(d)) << 32) | ~k
//   -> max packed = min d; equal d -> max ~k = min k.
// BM=128, BN=128, BK=32, 256 threads, 8x8 microtile.
// ============================================================================
__global__ __launch_bounds__(256) void score_argmin_kernel(
    const float* __restrict__ emb)
{
    __shared__ float As[32][132];   // [d][m]
    __shared__ float Bs[32][132];   // [d][k]
    __shared__ float bS[128];
    __shared__ float aS[128];

    const int tid = threadIdx.x;
    const int tx  = tid & 15;
    const int ty  = tid >> 4;
    const int m0  = blockIdx.x * 128;
    const int j0  = blockIdx.y * 128;

    if (tid < 128) { bS[tid] = g_b[j0 + tid]; aS[tid] = g_a[m0 + tid]; }

    float acc[8][8];
#pragma unroll
    for (int i = 0; i < 8; i++)
#pragma unroll
        for (int j = 0; j < 8; j++) acc[i][j] = 0.f;

    for (int k0 = 0; k0 < D_DIM; k0 += 32) {
#pragma unroll
        for (int r = 0; r < 4; r++) {
            int idx = tid + r * 256;          // 0..1023
            int row = idx >> 3;
            int kk  = (idx & 7) * 4;
            float4 v = *reinterpret_cast<const float4*>(
                &g_X[(size_t)(m0 + row) * D_DIM + k0 + kk]);
            As[kk + 0][row] = v.x; As[kk + 1][row] = v.y;
            As[kk + 2][row] = v.z; As[kk + 3][row] = v.w;
        }
#pragma unroll
        for (int r = 0; r < 4; r++) {
            int idx = tid + r * 256;
            int j  = idx >> 3;
            int kk = (idx & 7) * 4;
            float4 v = *reinterpret_cast<const float4*>(
                &emb[(size_t)(j0 + j) * D_DIM + k0 + kk]);
            Bs[kk + 0][j] = v.x; Bs[kk + 1][j] = v.y;
            Bs[kk + 2][j] = v.z; Bs[kk + 3][j] = v.w;
        }
        __syncthreads();
#pragma unroll
        for (int k = 0; k < 32; k++) {
            float4 a0 = *reinterpret_cast<const float4*>(&As[k][ty * 8]);
            float4 a1 = *reinterpret_cast<const float4*>(&As[k][ty * 8 + 4]);
            float4 b0 = *reinterpret_cast<const float4*>(&Bs[k][tx * 8]);
            float4 b1 = *reinterpret_cast<const float4*>(&Bs[k][tx * 8 + 4]);
            float a[8] = {a0.x, a0.y, a0.z, a0.w, a1.x, a1.y, a1.z, a1.w};
            float b[8] = {b0.x, b0.y, b0.z, b0.w, b1.x, b1.y, b1.z, b1.w};
#pragma unroll
            for (int i = 0; i < 8; i++)
#pragma unroll
                for (int j = 0; j < 8; j++) acc[i][j] = fmaf(a[i], b[j], acc[i][j]);
        }
        __syncthreads();
    }

    // epilogue: per-row argmin of rounded distance
#pragma unroll
    for (int i = 0; i < 8; i++) {
        float am = aS[ty * 8 + i];
        float bd = 0.f; int bk = -1;
#pragma unroll
        for (int j = 0; j < 8; j++) {
            int col = tx * 8 + j;
            float c  = __fmul_rn(2.0f, acc[i][j]);
            float dd = __fsub_rn(__fadd_rn(am, bS[col]), c);
            if (bk < 0 || dd < bd) { bd = dd; bk = j0 + col; }  // cols ascend
        }
        // reduce across the 16 lanes of this row
#pragma unroll
        for (int o = 8; o > 0; o >>= 1) {
            float od = __shfl_xor_sync(0xffffffffu, bd, o);
            int   ok = __shfl_xor_sync(0xffffffffu, bk, o);
            if (od < bd || (od == bd && ok < bk)) { bd = od; bk = ok; }
        }
        if (tx == 0) {
            unsigned u = __float_as_uint(bd);
            unsigned s = (u & 0x80000000u) ? ~u : (u | 0x80000000u); // asc sortable
            unsigned long long packed =
                ((unsigned long long)(~s) << 32) | (unsigned)(~(unsigned)bk);
            atomicMax(&g_best[m0 + ty * 8 + i], packed);
        }
    }
}

// ============================================================================
// Kernel 5: zero-fill the one-hot encodings block (268 MB)
// ============================================================================
__global__ void zero_enc_kernel(float4* __restrict__ enc4, size_t n4)
{
    size_t i = (size_t)blockIdx.x * blockDim.x + threadIdx.x;
    size_t stride = (size_t)gridDim.x * blockDim.x;
    float4 z = make_float4(0.f, 0.f, 0.f, 0.f);
    for (; i < n4; i += stride) enc4[i] = z;
}

// ============================================================================
// Kernel 6: finalize — quantized gather, index write, one-hot scatter.
// ============================================================================
__global__ __launch_bounds__(256) void finalize_kernel(
    const float* __restrict__ emb,
    float* __restrict__ quant,   // [N, D]
    float* __restrict__ idxout,  // [N]
    float* __restrict__ enc)     // [N, K]
{
    int w    = (blockIdx.x * blockDim.x + threadIdx.x) >> 5;
    int lane = threadIdx.x & 31;
    if (w >= N_ROWS) return;
    unsigned long long p = g_best[w];
    int k = (int)(~(unsigned)(p & 0xffffffffull));
    if (lane == 0) {
        idxout[w] = (float)k;
        enc[(size_t)w * K_CB + k] = 1.0f;
    }
    const float* src = emb + (size_t)k * D_DIM;
    float* dst = quant + (size_t)w * D_DIM;
#pragma unroll
    for (int r = 0; r < 2; r++) {
        int c = (lane + r * 32) * 4;
        *reinterpret_cast<float4*>(&dst[c]) =
            *reinterpret_cast<const float4*>(&src[c]);
    }
}

// ============================================================================
extern "C" void kernel_launch(void* const* d_in, const int* in_sizes, int n_in,
                              void* d_out, int out_size)
{
    const float* F     = (const float*)d_in[0];  // features [16384,512]
    const float* Wp    = (const float*)d_in[1];  // [256,512]
    const float* bp    = (const float*)d_in[2];  // [256]
    const float* gamma = (const float*)d_in[3];  // [256]
    const float* beta  = (const float*)d_in[4];  // [256]
    const float* emb   = (const float*)d_in[5];  // [4096,256]

    float* out    = (float*)d_out;
    float* quant  = out;                                   // N*D
    float* idxout = out + (size_t)N_ROWS * D_DIM;          // N
    float* enc    = idxout + N_ROWS;                       // N*K

    proj_ln_kernel<<<N_ROWS / 64, 256>>>(F, Wp, bp, gamma, beta);
    b_kernel<<<K_CB / 256, 256>>>(emb);
    a_kernel<<<N_ROWS / 256, 256>>>();
    score_argmin_kernel<<<dim3(N_ROWS / 128, K_CB / 128), 256>>>(emb);

    size_t enc_f4 = ((size_t)N_ROWS * K_CB) / 4;
    zero_enc_kernel<<<4096, 256>>>((float4*)enc, enc_f4);
    finalize_kernel<<<(N_ROWS * 32) / 256, 256>>>(emb, quant, idxout, enc);
}

// round 3
// speedup vs baseline: 2.1033x; 2.1033x over previous
#include <cuda_runtime.h>
#include <cuda_bf16.h>
#include <cstdint>

#define N_ROWS 16384
#define H_DIM  512
#define D_DIM  256
#define K_CB   4096
#define MARGIN 2.5e-3f

// -------- scratch (static device arrays; no cudaMalloc allowed) --------
__device__ float          g_X [N_ROWS * D_DIM];     // post-LN activations (fp32)
__device__ __nv_bfloat16  g_Xh[N_ROWS * D_DIM];     // bf16 copy for screen
__device__ __nv_bfloat16  g_Eh[K_CB   * D_DIM];     // bf16 codebook
__device__ float          g_a [N_ROWS];             // fl(sum u^2) per row
__device__ float          g_b [K_CB];               // ||e_k||^2
__device__ unsigned       g_mina[N_ROWS];           // approx row-min d (float bits)
__device__ float          g_S [(size_t)N_ROWS * K_CB]; // approx c = 2*dot (fp32)

// ============================================================================
// Kernel 1: projection GEMM + bias + LayerNorm (fused). Unchanged math from
// the bit-exact round-2 kernel; epilogue additionally stores bf16 copy.
// ============================================================================
__global__ __launch_bounds__(256) void proj_ln_kernel(
    const float* __restrict__ F, const float* __restrict__ Wp,
    const float* __restrict__ bp, const float* __restrict__ gamma,
    const float* __restrict__ beta)
{
    __shared__ float As[32][68];
    __shared__ float Bs[32][260];

    const int tid  = threadIdx.x;
    const int warp = tid >> 5;
    const int lane = tid & 31;
    const int m0   = blockIdx.x * 64;

    float acc[8][8];
#pragma unroll
    for (int i = 0; i < 8; i++)
#pragma unroll
        for (int j = 0; j < 8; j++) acc[i][j] = 0.f;

    for (int k0 = 0; k0 < H_DIM; k0 += 32) {
#pragma unroll
        for (int r = 0; r < 2; r++) {
            int idx = tid + r * 256;
            int row = idx >> 3;
            int kk  = (idx & 7) * 4;
            float4 v = *reinterpret_cast<const float4*>(
                &F[(size_t)(m0 + row) * H_DIM + k0 + kk]);
            As[kk + 0][row] = v.x; As[kk + 1][row] = v.y;
            As[kk + 2][row] = v.z; As[kk + 3][row] = v.w;
        }
#pragma unroll
        for (int r = 0; r < 8; r++) {
            int idx = tid + r * 256;
            int d  = idx >> 3;
            int kk = (idx & 7) * 4;
            float4 v = *reinterpret_cast<const float4*>(
                &Wp[(size_t)d * H_DIM + k0 + kk]);
            Bs[kk + 0][d] = v.x; Bs[kk + 1][d] = v.y;
            Bs[kk + 2][d] = v.z; Bs[kk + 3][d] = v.w;
        }
        __syncthreads();
#pragma unroll
        for (int k = 0; k < 32; k++) {
            float4 a0 = *reinterpret_cast<const float4*>(&As[k][warp * 8]);
            float4 a1 = *reinterpret_cast<const float4*>(&As[k][warp * 8 + 4]);
            float4 b0 = *reinterpret_cast<const float4*>(&Bs[k][lane * 8]);
            float4 b1 = *reinterpret_cast<const float4*>(&Bs[k][lane * 8 + 4]);
            float a[8] = {a0.x, a0.y, a0.z, a0.w, a1.x, a1.y, a1.z, a1.w};
            float b[8] = {b0.x, b0.y, b0.z, b0.w, b1.x, b1.y, b1.z, b1.w};
#pragma unroll
            for (int i = 0; i < 8; i++)
#pragma unroll
                for (int j = 0; j < 8; j++) acc[i][j] = fmaf(a[i], b[j], acc[i][j]);
        }
        __syncthreads();
    }

    float bpv[8], gv[8], bv[8];
#pragma unroll
    for (int j = 0; j < 8; j++) {
        int d = lane * 8 + j;
        bpv[j] = bp[d]; gv[j] = gamma[d]; bv[j] = beta[d];
    }
#pragma unroll
    for (int i = 0; i < 8; i++) {
#pragma unroll
        for (int j = 0; j < 8; j++) acc[i][j] += bpv[j];
        float s = 0.f;
#pragma unroll
        for (int j = 0; j < 8; j++) s += acc[i][j];
#pragma unroll
        for (int o = 16; o > 0; o >>= 1) s += __shfl_xor_sync(0xffffffffu, s, o);
        float mu = s * (1.f / 256.f);
        float ss = 0.f;
#pragma unroll
        for (int j = 0; j < 8; j++) { float d2 = acc[i][j] - mu; ss += d2 * d2; }
#pragma unroll
        for (int o = 16; o > 0; o >>= 1) ss += __shfl_xor_sync(0xffffffffu, ss, o);
        float var = ss * (1.f / 256.f);
        float rs  = rsqrtf(var + 1e-5f);
        int row = m0 + warp * 8 + i;
        float out[8];
#pragma unroll
        for (int j = 0; j < 8; j++)
            out[j] = (acc[i][j] - mu) * rs * gv[j] + bv[j];
        *reinterpret_cast<float4*>(&g_X[(size_t)row * D_DIM + lane * 8]) =
            make_float4(out[0], out[1], out[2], out[3]);
        *reinterpret_cast<float4*>(&g_X[(size_t)row * D_DIM + lane * 8 + 4]) =
            make_float4(out[4], out[5], out[6], out[7]);
        __nv_bfloat162 h[4];
        h[0] = __floats2bfloat162_rn(out[0], out[1]);
        h[1] = __floats2bfloat162_rn(out[2], out[3]);
        h[2] = __floats2bfloat162_rn(out[4], out[5]);
        h[3] = __floats2bfloat162_rn(out[6], out[7]);
        *reinterpret_cast<uint4*>(&g_Xh[(size_t)row * D_DIM + lane * 8]) =
            *reinterpret_cast<uint4*>(h);
    }
}

// ============================================================================
// Kernel 2: per-code ||e||^2 + bf16 conversion. One warp per codebook row.
// (b ~ 5e-6 << ulp(256)/2; its summation order is provably irrelevant.)
// ============================================================================
__global__ __launch_bounds__(256) void eb_kernel(const float* __restrict__ emb)
{
    int k    = (blockIdx.x * blockDim.x + threadIdx.x) >> 5;
    int lane = threadIdx.x & 31;
    if (k >= K_CB) return;
    const float* row = emb + (size_t)k * D_DIM;
    float4 v0 = *reinterpret_cast<const float4*>(&row[lane * 8]);
    float4 v1 = *reinterpret_cast<const float4*>(&row[lane * 8 + 4]);
    float s = v0.x * v0.x + v0.y * v0.y + v0.z * v0.z + v0.w * v0.w
            + v1.x * v1.x + v1.y * v1.y + v1.z * v1.z + v1.w * v1.w;
#pragma unroll
    for (int o = 16; o > 0; o >>= 1) s += __shfl_xor_sync(0xffffffffu, s, o);
    if (lane == 0) g_b[k] = s;
    __nv_bfloat162 h[4];
    h[0] = __floats2bfloat162_rn(v0.x, v0.y);
    h[1] = __floats2bfloat162_rn(v0.z, v0.w);
    h[2] = __floats2bfloat162_rn(v1.x, v1.y);
    h[3] = __floats2bfloat162_rn(v1.z, v1.w);
    *reinterpret_cast<uint4*>(&g_Eh[(size_t)k * D_DIM + lane * 8]) =
        *reinterpret_cast<uint4*>(h);
}

// ============================================================================
// Kernel 3: g_a[m] = fl-sequential sum of u^2 (bit-identical to round 2);
// also init g_mina to +inf bits.
// ============================================================================
__global__ __launch_bounds__(256) void a_kernel()
{
    int m = blockIdx.x * blockDim.x + threadIdx.x;
    if (m >= N_ROWS) return;
    const float* row = g_X + (size_t)m * D_DIM;
    float acc = 0.f;
#pragma unroll 8
    for (int d = 0; d < D_DIM; d++) {
        float v = row[d];
        acc = __fadd_rn(acc, __fmul_rn(v, v));
    }
    g_a[m] = acc;
    g_mina[m] = 0x7F800000u;   // +inf
}

// ============================================================================
// Kernel 4: SCREEN — bf16 mma.sync GEMM. Stores c~=2*dot (fp32) into g_S and
// the per-row approx-min distance into g_mina.
// BM=128, BN=64, BK=32, 8 warps (4x2), warp tile 32x32, m16n8k16 frags.
// ============================================================================
__device__ __forceinline__ void mma_bf16(float& d0, float& d1, float& d2, float& d3,
                                         uint32_t a0, uint32_t a1, uint32_t a2, uint32_t a3,
                                         uint32_t b0, uint32_t b1)
{
    asm volatile(
        "mma.sync.aligned.m16n8k16.row.col.f32.bf16.bf16.f32 "
        "{%0,%1,%2,%3}, {%4,%5,%6,%7}, {%8,%9}, {%0,%1,%2,%3};"
        : "+f"(d0), "+f"(d1), "+f"(d2), "+f"(d3)
        : "r"(a0), "r"(a1), "r"(a2), "r"(a3), "r"(b0), "r"(b1));
}

__device__ __forceinline__ void ldsm_x4(uint32_t& r0, uint32_t& r1,
                                        uint32_t& r2, uint32_t& r3,
                                        const __nv_bfloat16* p)
{
    uint32_t addr = (uint32_t)__cvta_generic_to_shared(p);
    asm volatile("ldmatrix.sync.aligned.m8n8.x4.shared.b16 {%0,%1,%2,%3}, [%4];"
                 : "=r"(r0), "=r"(r1), "=r"(r2), "=r"(r3) : "r"(addr));
}

__global__ __launch_bounds__(256) void screen_kernel()
{
    __shared__ __nv_bfloat16 Asm[128][40];   // +8 pad -> conflict-free
    __shared__ __nv_bfloat16 Bsm[64][40];
    __shared__ float aS[128];
    __shared__ float bS[64];

    const int tid  = threadIdx.x;
    const int warp = tid >> 5;
    const int lane = tid & 31;
    const int wm   = warp >> 1;      // 0..3
    const int wn   = warp & 1;       // 0..1
    const int m0   = blockIdx.x * 128;
    const int j0   = blockIdx.y * 64;

    if (tid < 128) aS[tid] = g_a[m0 + tid];
    else if (tid < 192) bS[tid - 128] = g_b[j0 + tid - 128];

    float acc[2][4][4];
#pragma unroll
    for (int mt = 0; mt < 2; mt++)
#pragma unroll
        for (int nn = 0; nn < 4; nn++)
#pragma unroll
            for (int c = 0; c < 4; c++) acc[mt][nn][c] = 0.f;

    for (int k0 = 0; k0 < D_DIM; k0 += 32) {
#pragma unroll
        for (int r = 0; r < 2; r++) {               // A: 512 uint4
            int i   = tid + r * 256;
            int row = i >> 2;
            int kk  = (i & 3) * 8;
            *reinterpret_cast<uint4*>(&Asm[row][kk]) =
                *reinterpret_cast<const uint4*>(
                    &g_Xh[(size_t)(m0 + row) * D_DIM + k0 + kk]);
        }
        {                                            // B: 256 uint4
            int row = tid >> 2;
            int kk  = (tid & 3) * 8;
            *reinterpret_cast<uint4*>(&Bsm[row][kk]) =
                *reinterpret_cast<const uint4*>(
                    &g_Eh[(size_t)(j0 + row) * D_DIM + k0 + kk]);
        }
        __syncthreads();
#pragma unroll
        for (int ks = 0; ks < 2; ks++) {
            const int krow = ks * 16;
            uint32_t a[2][4], b[2][4];
#pragma unroll
            for (int mt = 0; mt < 2; mt++) {
                const __nv_bfloat16* p =
                    &Asm[wm * 32 + mt * 16 + (lane & 15)][krow + (lane >> 4) * 8];
                ldsm_x4(a[mt][0], a[mt][1], a[mt][2], a[mt][3], p);
            }
#pragma unroll
            for (int nt = 0; nt < 2; nt++) {
                int nrow = wn * 32 + nt * 16 + (lane & 7) + ((lane >> 4) << 3);
                int kcol = krow + ((lane >> 3) & 1) * 8;
                ldsm_x4(b[nt][0], b[nt][1], b[nt][2], b[nt][3], &Bsm[nrow][kcol]);
            }
#pragma unroll
            for (int mt = 0; mt < 2; mt++)
#pragma unroll
                for (int nn = 0; nn < 4; nn++)
                    mma_bf16(acc[mt][nn][0], acc[mt][nn][1],
                             acc[mt][nn][2], acc[mt][nn][3],
                             a[mt][0], a[mt][1], a[mt][2], a[mt][3],
                             b[nn >> 1][(nn & 1) * 2], b[nn >> 1][(nn & 1) * 2 + 1]);
        }
        __syncthreads();
    }

    // epilogue: store c = 2*dot, track per-row approx min of d = (a+b) - c
    const int rbase = m0 + wm * 32 + (lane >> 2);
    const int cbase = j0 + wn * 32 + (lane & 3) * 2;
#pragma unroll
    for (int mt = 0; mt < 2; mt++) {
#pragma unroll
        for (int half = 0; half < 2; half++) {       // c0,c1 (row) / c2,c3 (row+8)
            int row = rbase + mt * 16 + half * 8;
            float dmin = 3.4e38f;
#pragma unroll
            for (int nn = 0; nn < 4; nn++) {
                int col = cbase + nn * 8;
                float c0 = 2.f * acc[mt][nn][half * 2 + 0];
                float c1 = 2.f * acc[mt][nn][half * 2 + 1];
                *reinterpret_cast<float2*>(&g_S[(size_t)row * K_CB + col]) =
                    make_float2(c0, c1);
                float ab = aS[row - m0];
                float d0 = __fsub_rn(__fadd_rn(ab, bS[col - j0]),     c0);
                float d1 = __fsub_rn(__fadd_rn(ab, bS[col - j0 + 1]), c1);
                dmin = fminf(dmin, fminf(d0, d1));
            }
            // reduce over the 4 lanes of this quad (same row)
            dmin = fminf(dmin, __shfl_xor_sync(0xffffffffu, dmin, 1));
            dmin = fminf(dmin, __shfl_xor_sync(0xffffffffu, dmin, 2));
            if ((lane & 3) == 0)
                atomicMin(&g_mina[row], __float_as_uint(dmin));   // d > 0 always
        }
    }
}

// ============================================================================
// Kernel 5: SELECT — per row: scan approx d, collect candidates within MARGIN
// of row min, rescore exactly in fp32 (round-2 rounding semantics + smallest-
// index tie-break), then write all three outputs for the row (enc zeros
// included — replaces the old memset + finalize kernels).
// ============================================================================
__global__ __launch_bounds__(128) void select_kernel(
    const float* __restrict__ emb,
    float* __restrict__ quant, float* __restrict__ idxout,
    float* __restrict__ enc)
{
    __shared__ float uS[D_DIM];
    __shared__ int   cand[1024];
    __shared__ int   ncand;
    __shared__ unsigned long long best;
    __shared__ int   winner;

    const int m    = blockIdx.x;
    const int tid  = threadIdx.x;
    const int lane = tid & 31;
    const int warp = tid >> 5;

    if (tid == 0) { ncand = 0; best = 0ull; }
    // load u row (fp32)
    {
        float4 v = *reinterpret_cast<const float4*>(&g_X[(size_t)m * D_DIM + tid * 2]);
        // 128 threads * 2 floats = 256
        uS[tid * 2]     = v.x;  // NOTE: float4 load of 2? fix below
        uS[tid * 2 + 1] = v.y;
    }
    const float a   = g_a[m];
    const float thr = __uint_as_float(g_mina[m]) + MARGIN;
    __syncthreads();

    // scan c row, write enc zeros, collect candidates
    const float* crow = &g_S[(size_t)m * K_CB];
    float* erow = &enc[(size_t)m * K_CB];
#pragma unroll
    for (int base = 0; base < K_CB; base += 512) {
        int idx = base + tid * 4;
        float4 c4 = *reinterpret_cast<const float4*>(&crow[idx]);
        float4 b4 = *reinterpret_cast<const float4*>(&g_b[idx]);
        float d0 = __fsub_rn(__fadd_rn(a, b4.x), c4.x);
        float d1 = __fsub_rn(__fadd_rn(a, b4.y), c4.y);
        float d2 = __fsub_rn(__fadd_rn(a, b4.z), c4.z);
        float d3 = __fsub_rn(__fadd_rn(a, b4.w), c4.w);
        if (d0 <= thr) { int p = atomicAdd(&ncand, 1); if (p < 1024) cand[p] = idx; }
        if (d1 <= thr) { int p = atomicAdd(&ncand, 1); if (p < 1024) cand[p] = idx + 1; }
        if (d2 <= thr) { int p = atomicAdd(&ncand, 1); if (p < 1024) cand[p] = idx + 2; }
        if (d3 <= thr) { int p = atomicAdd(&ncand, 1); if (p < 1024) cand[p] = idx + 3; }
        *reinterpret_cast<float4*>(&erow[idx]) = make_float4(0.f, 0.f, 0.f, 0.f);
    }
    __syncthreads();

    const int nc = min(ncand, 1024);
    // exact rescore: one warp per candidate
    for (int ci = warp; ci < nc; ci += 4) {
        int k = cand[ci];
        const float* e = emb + (size_t)k * D_DIM;
        float4 u0 = *reinterpret_cast<const float4*>(&uS[lane * 8]);
        float4 u1 = *reinterpret_cast<const float4*>(&uS[lane * 8 + 4]);
        float4 e0 = *reinterpret_cast<const float4*>(&e[lane * 8]);
        float4 e1 = *reinterpret_cast<const float4*>(&e[lane * 8 + 4]);
        float dot = 0.f;
        dot = fmaf(u0.x, e0.x, dot); dot = fmaf(u0.y, e0.y, dot);
        dot = fmaf(u0.z, e0.z, dot); dot = fmaf(u0.w, e0.w, dot);
        dot = fmaf(u1.x, e1.x, dot); dot = fmaf(u1.y, e1.y, dot);
        dot = fmaf(u1.z, e1.z, dot); dot = fmaf(u1.w, e1.w, dot);
#pragma unroll
        for (int o = 16; o > 0; o >>= 1)
            dot = __fadd_rn(dot, __shfl_xor_sync(0xffffffffu, dot, o));
        if (lane == 0) {
            float c  = __fmul_rn(2.0f, dot);
            float dd = __fsub_rn(__fadd_rn(a, g_b[k]), c);
            unsigned u = __float_as_uint(dd);
            unsigned s = (u & 0x80000000u) ? ~u : (u | 0x80000000u);
            unsigned long long packed =
                ((unsigned long long)(~s) << 32) | (unsigned)(~(unsigned)k);
            atomicMax(&best, packed);
        }
    }
    __syncthreads();
    if (tid == 0) {
        int k = (int)(~(unsigned)(best & 0xffffffffull));
        winner = k;
        idxout[m] = (float)k;
        erow[k] = 1.0f;
    }
    __syncthreads();
    // quant gather
    const int k = winner;
    if (tid < 64) {
        *reinterpret_cast<float4*>(&quant[(size_t)m * D_DIM + tid * 4]) =
            *reinterpret_cast<const float4*>(&emb[(size_t)k * D_DIM + tid * 4]);
    }
}

// ============================================================================
extern "C" void kernel_launch(void* const* d_in, const int* in_sizes, int n_in,
                              void* d_out, int out_size)
{
    const float* F     = (const float*)d_in[0];
    const float* Wp    = (const float*)d_in[1];
    const float* bp    = (const float*)d_in[2];
    const float* gamma = (const float*)d_in[3];
    const float* beta  = (const float*)d_in[4];
    const float* emb   = (const float*)d_in[5];

    float* out    = (float*)d_out;
    float* quant  = out;
    float* idxout = out + (size_t)N_ROWS * D_DIM;
    float* enc    = idxout + N_ROWS;

    proj_ln_kernel<<<N_ROWS / 64, 256>>>(F, Wp, bp, gamma, beta);
    eb_kernel<<<(K_CB * 32) / 256, 256>>>(emb);
    a_kernel<<<N_ROWS / 256, 256>>>();
    screen_kernel<<<dim3(N_ROWS / 128, K_CB / 64), 256>>>();
    select_kernel<<<N_ROWS, 128>>>(emb, quant, idxout, enc);
}

// round 4
// speedup vs baseline: 2.4155x; 1.1484x over previous
#include <cuda_runtime.h>
#include <cuda_bf16.h>
#include <cuda_fp16.h>
#include <cstdint>

#define N_ROWS 16384
#define H_DIM  512
#define D_DIM  256
#define K_CB   4096
#define MARGIN 2.5e-3f

// -------- scratch (static device arrays; no cudaMalloc allowed) --------
__device__ float          g_X [N_ROWS * D_DIM];     // post-LN activations (fp32)
__device__ __nv_bfloat16  g_Xh[N_ROWS * D_DIM];     // bf16 copy for screen
__device__ __nv_bfloat16  g_Eh[K_CB   * D_DIM];     // bf16 codebook
__device__ float          g_a [N_ROWS];             // fl(sum u^2) per row
__device__ float          g_b [K_CB];               // ||e_k||^2
__device__ unsigned       g_mina[N_ROWS];           // approx row-min d (float bits)
__device__ __half         g_Sh[(size_t)N_ROWS * K_CB]; // s = b - 2*dot (fp16)

// ============================================================================
// Kernel 1: projection GEMM + bias + LayerNorm (fused). NUMERICS FROZEN.
// ============================================================================
__global__ __launch_bounds__(256) void proj_ln_kernel(
    const float* __restrict__ F, const float* __restrict__ Wp,
    const float* __restrict__ bp, const float* __restrict__ gamma,
    const float* __restrict__ beta)
{
    __shared__ float As[32][68];
    __shared__ float Bs[32][260];

    const int tid  = threadIdx.x;
    const int warp = tid >> 5;
    const int lane = tid & 31;
    const int m0   = blockIdx.x * 64;

    float acc[8][8];
#pragma unroll
    for (int i = 0; i < 8; i++)
#pragma unroll
        for (int j = 0; j < 8; j++) acc[i][j] = 0.f;

    for (int k0 = 0; k0 < H_DIM; k0 += 32) {
#pragma unroll
        for (int r = 0; r < 2; r++) {
            int idx = tid + r * 256;
            int row = idx >> 3;
            int kk  = (idx & 7) * 4;
            float4 v = *reinterpret_cast<const float4*>(
                &F[(size_t)(m0 + row) * H_DIM + k0 + kk]);
            As[kk + 0][row] = v.x; As[kk + 1][row] = v.y;
            As[kk + 2][row] = v.z; As[kk + 3][row] = v.w;
        }
#pragma unroll
        for (int r = 0; r < 8; r++) {
            int idx = tid + r * 256;
            int d  = idx >> 3;
            int kk = (idx & 7) * 4;
            float4 v = *reinterpret_cast<const float4*>(
                &Wp[(size_t)d * H_DIM + k0 + kk]);
            Bs[kk + 0][d] = v.x; Bs[kk + 1][d] = v.y;
            Bs[kk + 2][d] = v.z; Bs[kk + 3][d] = v.w;
        }
        __syncthreads();
#pragma unroll
        for (int k = 0; k < 32; k++) {
            float4 a0 = *reinterpret_cast<const float4*>(&As[k][warp * 8]);
            float4 a1 = *reinterpret_cast<const float4*>(&As[k][warp * 8 + 4]);
            float4 b0 = *reinterpret_cast<const float4*>(&Bs[k][lane * 8]);
            float4 b1 = *reinterpret_cast<const float4*>(&Bs[k][lane * 8 + 4]);
            float a[8] = {a0.x, a0.y, a0.z, a0.w, a1.x, a1.y, a1.z, a1.w};
            float b[8] = {b0.x, b0.y, b0.z, b0.w, b1.x, b1.y, b1.z, b1.w};
#pragma unroll
            for (int i = 0; i < 8; i++)
#pragma unroll
                for (int j = 0; j < 8; j++) acc[i][j] = fmaf(a[i], b[j], acc[i][j]);
        }
        __syncthreads();
    }

    float bpv[8], gv[8], bv[8];
#pragma unroll
    for (int j = 0; j < 8; j++) {
        int d = lane * 8 + j;
        bpv[j] = bp[d]; gv[j] = gamma[d]; bv[j] = beta[d];
    }
#pragma unroll
    for (int i = 0; i < 8; i++) {
#pragma unroll
        for (int j = 0; j < 8; j++) acc[i][j] += bpv[j];
        float s = 0.f;
#pragma unroll
        for (int j = 0; j < 8; j++) s += acc[i][j];
#pragma unroll
        for (int o = 16; o > 0; o >>= 1) s += __shfl_xor_sync(0xffffffffu, s, o);
        float mu = s * (1.f / 256.f);
        float ss = 0.f;
#pragma unroll
        for (int j = 0; j < 8; j++) { float d2 = acc[i][j] - mu; ss += d2 * d2; }
#pragma unroll
        for (int o = 16; o > 0; o >>= 1) ss += __shfl_xor_sync(0xffffffffu, ss, o);
        float var = ss * (1.f / 256.f);
        float rs  = rsqrtf(var + 1e-5f);
        int row = m0 + warp * 8 + i;
        float out[8];
#pragma unroll
        for (int j = 0; j < 8; j++)
            out[j] = (acc[i][j] - mu) * rs * gv[j] + bv[j];
        *reinterpret_cast<float4*>(&g_X[(size_t)row * D_DIM + lane * 8]) =
            make_float4(out[0], out[1], out[2], out[3]);
        *reinterpret_cast<float4*>(&g_X[(size_t)row * D_DIM + lane * 8 + 4]) =
            make_float4(out[4], out[5], out[6], out[7]);
        __nv_bfloat162 h[4];
        h[0] = __floats2bfloat162_rn(out[0], out[1]);
        h[1] = __floats2bfloat162_rn(out[2], out[3]);
        h[2] = __floats2bfloat162_rn(out[4], out[5]);
        h[3] = __floats2bfloat162_rn(out[6], out[7]);
        *reinterpret_cast<uint4*>(&g_Xh[(size_t)row * D_DIM + lane * 8]) =
            *reinterpret_cast<uint4*>(h);
    }
}

// ============================================================================
// Kernel 2: per-code ||e||^2 + bf16 conversion. One warp per codebook row.
// ============================================================================
__global__ __launch_bounds__(256) void eb_kernel(const float* __restrict__ emb)
{
    int k    = (blockIdx.x * blockDim.x + threadIdx.x) >> 5;
    int lane = threadIdx.x & 31;
    if (k >= K_CB) return;
    const float* row = emb + (size_t)k * D_DIM;
    float4 v0 = *reinterpret_cast<const float4*>(&row[lane * 8]);
    float4 v1 = *reinterpret_cast<const float4*>(&row[lane * 8 + 4]);
    float s = v0.x * v0.x + v0.y * v0.y + v0.z * v0.z + v0.w * v0.w
            + v1.x * v1.x + v1.y * v1.y + v1.z * v1.z + v1.w * v1.w;
#pragma unroll
    for (int o = 16; o > 0; o >>= 1) s += __shfl_xor_sync(0xffffffffu, s, o);
    if (lane == 0) g_b[k] = s;
    __nv_bfloat162 h[4];
    h[0] = __floats2bfloat162_rn(v0.x, v0.y);
    h[1] = __floats2bfloat162_rn(v0.z, v0.w);
    h[2] = __floats2bfloat162_rn(v1.x, v1.y);
    h[3] = __floats2bfloat162_rn(v1.z, v1.w);
    *reinterpret_cast<uint4*>(&g_Eh[(size_t)k * D_DIM + lane * 8]) =
        *reinterpret_cast<uint4*>(h);
}

// ============================================================================
// Kernel 3: g_a[m] = fl-sequential sum of u^2 (NUMERICS FROZEN); init g_mina.
// ============================================================================
__global__ __launch_bounds__(256) void a_kernel()
{
    int m = blockIdx.x * blockDim.x + threadIdx.x;
    if (m >= N_ROWS) return;
    const float* row = g_X + (size_t)m * D_DIM;
    float acc = 0.f;
#pragma unroll 8
    for (int d = 0; d < D_DIM; d++) {
        float v = row[d];
        acc = __fadd_rn(acc, __fmul_rn(v, v));
    }
    g_a[m] = acc;
    g_mina[m] = 0x7F800000u;   // +inf
}

// ============================================================================
// Kernel 4: SCREEN v2 — bf16 mma.sync, BM=128, BN=128, BK=32.
// 8 warps: wm=warp>>1 (4 x 32 rows), wn=warp&1 (2 x 64 cols).
// Warp tile 32x64 -> 16 MMAs per 6 ldsm.x4 per k-step.
// Stores s = b - 2*dot as fp16; per-row min via smem then 1 global atomicMin.
// ============================================================================
__device__ __forceinline__ void mma_bf16(float& d0, float& d1, float& d2, float& d3,
                                         uint32_t a0, uint32_t a1, uint32_t a2, uint32_t a3,
                                         uint32_t b0, uint32_t b1)
{
    asm volatile(
        "mma.sync.aligned.m16n8k16.row.col.f32.bf16.bf16.f32 "
        "{%0,%1,%2,%3}, {%4,%5,%6,%7}, {%8,%9}, {%0,%1,%2,%3};"
        : "+f"(d0), "+f"(d1), "+f"(d2), "+f"(d3)
        : "r"(a0), "r"(a1), "r"(a2), "r"(a3), "r"(b0), "r"(b1));
}

__device__ __forceinline__ void ldsm_x4(uint32_t& r0, uint32_t& r1,
                                        uint32_t& r2, uint32_t& r3,
                                        const __nv_bfloat16* p)
{
    uint32_t addr = (uint32_t)__cvta_generic_to_shared(p);
    asm volatile("ldmatrix.sync.aligned.m8n8.x4.shared.b16 {%0,%1,%2,%3}, [%4];"
                 : "=r"(r0), "=r"(r1), "=r"(r2), "=r"(r3) : "r"(addr));
}

__global__ __launch_bounds__(256) void screen_kernel()
{
    __shared__ __nv_bfloat16 Asm[128][40];
    __shared__ __nv_bfloat16 Bsm[128][40];
    __shared__ float aS[128];
    __shared__ float bS[128];
    __shared__ unsigned rowminS[128];

    const int tid  = threadIdx.x;
    const int warp = tid >> 5;
    const int lane = tid & 31;
    const int wm   = warp >> 1;      // 0..3 -> 32 rows each
    const int wn   = warp & 1;       // 0..1 -> 64 cols each
    const int m0   = blockIdx.x * 128;
    const int j0   = blockIdx.y * 128;

    if (tid < 128) {
        aS[tid] = g_a[m0 + tid];
        bS[tid] = g_b[j0 + tid];
        rowminS[tid] = 0x7F800000u;
    }

    float acc[2][8][4];
#pragma unroll
    for (int mt = 0; mt < 2; mt++)
#pragma unroll
        for (int nn = 0; nn < 8; nn++)
#pragma unroll
            for (int c = 0; c < 4; c++) acc[mt][nn][c] = 0.f;

    for (int k0 = 0; k0 < D_DIM; k0 += 32) {
#pragma unroll
        for (int r = 0; r < 2; r++) {               // A: 512 uint4
            int i   = tid + r * 256;
            int row = i >> 2;
            int kk  = (i & 3) * 8;
            *reinterpret_cast<uint4*>(&Asm[row][kk]) =
                *reinterpret_cast<const uint4*>(
                    &g_Xh[(size_t)(m0 + row) * D_DIM + k0 + kk]);
        }
#pragma unroll
        for (int r = 0; r < 2; r++) {               // B: 512 uint4
            int i   = tid + r * 256;
            int row = i >> 2;
            int kk  = (i & 3) * 8;
            *reinterpret_cast<uint4*>(&Bsm[row][kk]) =
                *reinterpret_cast<const uint4*>(
                    &g_Eh[(size_t)(j0 + row) * D_DIM + k0 + kk]);
        }
        __syncthreads();
#pragma unroll
        for (int ks = 0; ks < 2; ks++) {
            const int krow = ks * 16;
            uint32_t a[2][4], b[4][4];
#pragma unroll
            for (int mt = 0; mt < 2; mt++) {
                const __nv_bfloat16* p =
                    &Asm[wm * 32 + mt * 16 + (lane & 15)][krow + (lane >> 4) * 8];
                ldsm_x4(a[mt][0], a[mt][1], a[mt][2], a[mt][3], p);
            }
#pragma unroll
            for (int nt = 0; nt < 4; nt++) {
                int nrow = wn * 64 + nt * 16 + (lane & 7) + ((lane >> 4) << 3);
                int kcol = krow + ((lane >> 3) & 1) * 8;
                ldsm_x4(b[nt][0], b[nt][1], b[nt][2], b[nt][3], &Bsm[nrow][kcol]);
            }
#pragma unroll
            for (int mt = 0; mt < 2; mt++)
#pragma unroll
                for (int nn = 0; nn < 8; nn++)
                    mma_bf16(acc[mt][nn][0], acc[mt][nn][1],
                             acc[mt][nn][2], acc[mt][nn][3],
                             a[mt][0], a[mt][1], a[mt][2], a[mt][3],
                             b[nn >> 1][(nn & 1) * 2], b[nn >> 1][(nn & 1) * 2 + 1]);
        }
        __syncthreads();
    }

    // epilogue: store s = b - 2*dot (fp16); track per-row approx-min of a+s
#pragma unroll
    for (int mt = 0; mt < 2; mt++) {
#pragma unroll
        for (int half = 0; half < 2; half++) {
            int lrow = wm * 32 + mt * 16 + half * 8 + (lane >> 2);
            int grow = m0 + lrow;
            float av = aS[lrow];
            float dmin = 3.4e38f;
#pragma unroll
            for (int nn = 0; nn < 8; nn++) {
                int lcol = wn * 64 + nn * 8 + (lane & 3) * 2;
                float s0 = bS[lcol]     - 2.f * acc[mt][nn][half * 2 + 0];
                float s1 = bS[lcol + 1] - 2.f * acc[mt][nn][half * 2 + 1];
                __half2 h = __floats2half2_rn(s0, s1);
                *reinterpret_cast<__half2*>(&g_Sh[(size_t)grow * K_CB + j0 + lcol]) = h;
                dmin = fminf(dmin, fminf(av + s0, av + s1));
            }
            dmin = fminf(dmin, __shfl_xor_sync(0xffffffffu, dmin, 1));
            dmin = fminf(dmin, __shfl_xor_sync(0xffffffffu, dmin, 2));
            if ((lane & 3) == 0)
                atomicMin(&rowminS[lrow], __float_as_uint(dmin));
        }
    }
    __syncthreads();
    if (tid < 128) atomicMin(&g_mina[m0 + tid], rowminS[tid]);
}

// ============================================================================
// Kernel 5: SELECT — scan fp16 s row, candidates within MARGIN of approx min,
// exact fp32 rescore (FROZEN rounding semantics + smallest-index tie-break),
// write all outputs for the row (enc zeros fused).
// ============================================================================
__global__ __launch_bounds__(128) void select_kernel(
    const float* __restrict__ emb,
    float* __restrict__ quant, float* __restrict__ idxout,
    float* __restrict__ enc)
{
    __shared__ float uS[D_DIM];
    __shared__ int   cand[1024];
    __shared__ int   ncand;
    __shared__ unsigned long long best;
    __shared__ int   winner;

    const int m    = blockIdx.x;
    const int tid  = threadIdx.x;
    const int lane = tid & 31;
    const int warp = tid >> 5;

    if (tid == 0) { ncand = 0; best = 0ull; }
    {
        float2 v = *reinterpret_cast<const float2*>(&g_X[(size_t)m * D_DIM + tid * 2]);
        uS[tid * 2]     = v.x;
        uS[tid * 2 + 1] = v.y;
    }
    const float a   = g_a[m];
    const float thr = __uint_as_float(g_mina[m]) + MARGIN;
    __syncthreads();

    const __half* srow = &g_Sh[(size_t)m * K_CB];
    float* erow = &enc[(size_t)m * K_CB];
#pragma unroll
    for (int base = 0; base < K_CB; base += 512) {
        int idx = base + tid * 4;
        uint2 raw = *reinterpret_cast<const uint2*>(&srow[idx]);
        __half2 h01 = *reinterpret_cast<__half2*>(&raw.x);
        __half2 h23 = *reinterpret_cast<__half2*>(&raw.y);
        float2 s01 = __half22float2(h01);
        float2 s23 = __half22float2(h23);
        float d0 = a + s01.x, d1 = a + s01.y;
        float d2 = a + s23.x, d3 = a + s23.y;
        if (d0 <= thr) { int p = atomicAdd(&ncand, 1); if (p < 1024) cand[p] = idx; }
        if (d1 <= thr) { int p = atomicAdd(&ncand, 1); if (p < 1024) cand[p] = idx + 1; }
        if (d2 <= thr) { int p = atomicAdd(&ncand, 1); if (p < 1024) cand[p] = idx + 2; }
        if (d3 <= thr) { int p = atomicAdd(&ncand, 1); if (p < 1024) cand[p] = idx + 3; }
        *reinterpret_cast<float4*>(&erow[idx]) = make_float4(0.f, 0.f, 0.f, 0.f);
    }
    __syncthreads();

    const int nc = min(ncand, 1024);
    for (int ci = warp; ci < nc; ci += 4) {
        int k = cand[ci];
        const float* e = emb + (size_t)k * D_DIM;
        float4 u0 = *reinterpret_cast<const float4*>(&uS[lane * 8]);
        float4 u1 = *reinterpret_cast<const float4*>(&uS[lane * 8 + 4]);
        float4 e0 = *reinterpret_cast<const float4*>(&e[lane * 8]);
        float4 e1 = *reinterpret_cast<const float4*>(&e[lane * 8 + 4]);
        float dot = 0.f;
        dot = fmaf(u0.x, e0.x, dot); dot = fmaf(u0.y, e0.y, dot);
        dot = fmaf(u0.z, e0.z, dot); dot = fmaf(u0.w, e0.w, dot);
        dot = fmaf(u1.x, e1.x, dot); dot = fmaf(u1.y, e1.y, dot);
        dot = fmaf(u1.z, e1.z, dot); dot = fmaf(u1.w, e1.w, dot);
#pragma unroll
        for (int o = 16; o > 0; o >>= 1)
            dot = __fadd_rn(dot, __shfl_xor_sync(0xffffffffu, dot, o));
        if (lane == 0) {
            float c  = __fmul_rn(2.0f, dot);
            float dd = __fsub_rn(__fadd_rn(a, g_b[k]), c);
            unsigned u = __float_as_uint(dd);
            unsigned s = (u & 0x80000000u) ? ~u : (u | 0x80000000u);
            unsigned long long packed =
                ((unsigned long long)(~s) << 32) | (unsigned)(~(unsigned)k);
            atomicMax(&best, packed);
        }
    }
    __syncthreads();
    if (tid == 0) {
        int k = (int)(~(unsigned)(best & 0xffffffffull));
        winner = k;
        idxout[m] = (float)k;
        erow[k] = 1.0f;
    }
    __syncthreads();
    const int k = winner;
    if (tid < 64) {
        *reinterpret_cast<float4*>(&quant[(size_t)m * D_DIM + tid * 4]) =
            *reinterpret_cast<const float4*>(&emb[(size_t)k * D_DIM + tid * 4]);
    }
}

// ============================================================================
extern "C" void kernel_launch(void* const* d_in, const int* in_sizes, int n_in,
                              void* d_out, int out_size)
{
    const float* F     = (const float*)d_in[0];
    const float* Wp    = (const float*)d_in[1];
    const float* bp    = (const float*)d_in[2];
    const float* gamma = (const float*)d_in[3];
    const float* beta  = (const float*)d_in[4];
    const float* emb   = (const float*)d_in[5];

    float* out    = (float*)d_out;
    float* quant  = out;
    float* idxout = out + (size_t)N_ROWS * D_DIM;
    float* enc    = idxout + N_ROWS;

    proj_ln_kernel<<<N_ROWS / 64, 256>>>(F, Wp, bp, gamma, beta);
    eb_kernel<<<(K_CB * 32) / 256, 256>>>(emb);
    a_kernel<<<N_ROWS / 256, 256>>>();
    screen_kernel<<<dim3(N_ROWS / 128, K_CB / 128), 256>>>();
    select_kernel<<<N_ROWS, 128>>>(emb, quant, idxout, enc);
}

// round 6
// speedup vs baseline: 2.5755x; 1.0662x over previous
#include <cuda_runtime.h>
#include <cuda_bf16.h>
#include <cuda_fp16.h>
#include <cstdint>

#define N_ROWS 16384
#define H_DIM  512
#define D_DIM  256
#define K_CB   4096
#define MARGIN 2.5e-3f

// -------- scratch (static device arrays; no cudaMalloc allowed) --------
__device__ float          g_X [N_ROWS * D_DIM];     // post-LN activations (fp32)
__device__ __nv_bfloat16  g_Xh[N_ROWS * D_DIM];     // bf16 copy for screen
__device__ __nv_bfloat16  g_Eh[K_CB   * D_DIM];     // bf16 codebook
__device__ float          g_a [N_ROWS];             // fl(sum u^2) per row
__device__ float          g_b [K_CB];               // ||e_k||^2
__device__ unsigned       g_mina[N_ROWS];           // approx row-min d (float bits)
__device__ __half         g_Sh[(size_t)N_ROWS * K_CB]; // s = b - 2*dot (fp16)

// ============================================================================
// Kernel 1: projection GEMM + bias + LayerNorm (fused). NUMERICS FROZEN.
// ============================================================================
__global__ __launch_bounds__(256) void proj_ln_kernel(
    const float* __restrict__ F, const float* __restrict__ Wp,
    const float* __restrict__ bp, const float* __restrict__ gamma,
    const float* __restrict__ beta)
{
    __shared__ float As[32][68];
    __shared__ float Bs[32][260];

    const int tid  = threadIdx.x;
    const int warp = tid >> 5;
    const int lane = tid & 31;
    const int m0   = blockIdx.x * 64;

    float acc[8][8];
#pragma unroll
    for (int i = 0; i < 8; i++)
#pragma unroll
        for (int j = 0; j < 8; j++) acc[i][j] = 0.f;

    for (int k0 = 0; k0 < H_DIM; k0 += 32) {
#pragma unroll
        for (int r = 0; r < 2; r++) {
            int idx = tid + r * 256;
            int row = idx >> 3;
            int kk  = (idx & 7) * 4;
            float4 v = *reinterpret_cast<const float4*>(
                &F[(size_t)(m0 + row) * H_DIM + k0 + kk]);
            As[kk + 0][row] = v.x; As[kk + 1][row] = v.y;
            As[kk + 2][row] = v.z; As[kk + 3][row] = v.w;
        }
#pragma unroll
        for (int r = 0; r < 8; r++) {
            int idx = tid + r * 256;
            int d  = idx >> 3;
            int kk = (idx & 7) * 4;
            float4 v = *reinterpret_cast<const float4*>(
                &Wp[(size_t)d * H_DIM + k0 + kk]);
            Bs[kk + 0][d] = v.x; Bs[kk + 1][d] = v.y;
            Bs[kk + 2][d] = v.z; Bs[kk + 3][d] = v.w;
        }
        __syncthreads();
#pragma unroll
        for (int k = 0; k < 32; k++) {
            float4 a0 = *reinterpret_cast<const float4*>(&As[k][warp * 8]);
            float4 a1 = *reinterpret_cast<const float4*>(&As[k][warp * 8 + 4]);
            float4 b0 = *reinterpret_cast<const float4*>(&Bs[k][lane * 8]);
            float4 b1 = *reinterpret_cast<const float4*>(&Bs[k][lane * 8 + 4]);
            float a[8] = {a0.x, a0.y, a0.z, a0.w, a1.x, a1.y, a1.z, a1.w};
            float b[8] = {b0.x, b0.y, b0.z, b0.w, b1.x, b1.y, b1.z, b1.w};
#pragma unroll
            for (int i = 0; i < 8; i++)
#pragma unroll
                for (int j = 0; j < 8; j++) acc[i][j] = fmaf(a[i], b[j], acc[i][j]);
        }
        __syncthreads();
    }

    float bpv[8], gv[8], bv[8];
#pragma unroll
    for (int j = 0; j < 8; j++) {
        int d = lane * 8 + j;
        bpv[j] = bp[d]; gv[j] = gamma[d]; bv[j] = beta[d];
    }
#pragma unroll
    for (int i = 0; i < 8; i++) {
#pragma unroll
        for (int j = 0; j < 8; j++) acc[i][j] += bpv[j];
        float s = 0.f;
#pragma unroll
        for (int j = 0; j < 8; j++) s += acc[i][j];
#pragma unroll
        for (int o = 16; o > 0; o >>= 1) s += __shfl_xor_sync(0xffffffffu, s, o);
        float mu = s * (1.f / 256.f);
        float ss = 0.f;
#pragma unroll
        for (int j = 0; j < 8; j++) { float d2 = acc[i][j] - mu; ss += d2 * d2; }
#pragma unroll
        for (int o = 16; o > 0; o >>= 1) ss += __shfl_xor_sync(0xffffffffu, ss, o);
        float var = ss * (1.f / 256.f);
        float rs  = rsqrtf(var + 1e-5f);
        int row = m0 + warp * 8 + i;
        float out[8];
#pragma unroll
        for (int j = 0; j < 8; j++)
            out[j] = (acc[i][j] - mu) * rs * gv[j] + bv[j];
        *reinterpret_cast<float4*>(&g_X[(size_t)row * D_DIM + lane * 8]) =
            make_float4(out[0], out[1], out[2], out[3]);
        *reinterpret_cast<float4*>(&g_X[(size_t)row * D_DIM + lane * 8 + 4]) =
            make_float4(out[4], out[5], out[6], out[7]);
        __nv_bfloat162 h[4];
        h[0] = __floats2bfloat162_rn(out[0], out[1]);
        h[1] = __floats2bfloat162_rn(out[2], out[3]);
        h[2] = __floats2bfloat162_rn(out[4], out[5]);
        h[3] = __floats2bfloat162_rn(out[6], out[7]);
        *reinterpret_cast<uint4*>(&g_Xh[(size_t)row * D_DIM + lane * 8]) =
            *reinterpret_cast<uint4*>(h);
    }
}

// ============================================================================
// Kernel 2: per-code ||e||^2 + bf16 conversion.
// ============================================================================
__global__ __launch_bounds__(256) void eb_kernel(const float* __restrict__ emb)
{
    int k    = (blockIdx.x * blockDim.x + threadIdx.x) >> 5;
    int lane = threadIdx.x & 31;
    if (k >= K_CB) return;
    const float* row = emb + (size_t)k * D_DIM;
    float4 v0 = *reinterpret_cast<const float4*>(&row[lane * 8]);
    float4 v1 = *reinterpret_cast<const float4*>(&row[lane * 8 + 4]);
    float s = v0.x * v0.x + v0.y * v0.y + v0.z * v0.z + v0.w * v0.w
            + v1.x * v1.x + v1.y * v1.y + v1.z * v1.z + v1.w * v1.w;
#pragma unroll
    for (int o = 16; o > 0; o >>= 1) s += __shfl_xor_sync(0xffffffffu, s, o);
    if (lane == 0) g_b[k] = s;
    __nv_bfloat162 h[4];
    h[0] = __floats2bfloat162_rn(v0.x, v0.y);
    h[1] = __floats2bfloat162_rn(v0.z, v0.w);
    h[2] = __floats2bfloat162_rn(v1.x, v1.y);
    h[3] = __floats2bfloat162_rn(v1.z, v1.w);
    *reinterpret_cast<uint4*>(&g_Eh[(size_t)k * D_DIM + lane * 8]) =
        *reinterpret_cast<uint4*>(h);
}

// ============================================================================
// Kernel 3: g_a[m] (NUMERICS FROZEN); init g_mina.
// ============================================================================
__global__ __launch_bounds__(256) void a_kernel()
{
    int m = blockIdx.x * blockDim.x + threadIdx.x;
    if (m >= N_ROWS) return;
    const float* row = g_X + (size_t)m * D_DIM;
    float acc = 0.f;
#pragma unroll 8
    for (int d = 0; d < D_DIM; d++) {
        float v = row[d];
        acc = __fadd_rn(acc, __fmul_rn(v, v));
    }
    g_a[m] = acc;
    g_mina[m] = 0x7F800000u;   // +inf
}

// ============================================================================
// Kernel 4: SCREEN v4 — bf16 mma.sync + cp.async double-buffered pipeline.
// BM=128, BN=128, BK=32, 2 stages. 8 warps, warp tile 32x64 (same frag
// pattern as the validated round-4 kernel). Smem pitch 40 (conflict-free).
// ============================================================================
__device__ __forceinline__ void mma_bf16(float& d0, float& d1, float& d2, float& d3,
                                         uint32_t a0, uint32_t a1, uint32_t a2, uint32_t a3,
                                         uint32_t b0, uint32_t b1)
{
    asm volatile(
        "mma.sync.aligned.m16n8k16.row.col.f32.bf16.bf16.f32 "
        "{%0,%1,%2,%3}, {%4,%5,%6,%7}, {%8,%9}, {%0,%1,%2,%3};"
        : "+f"(d0), "+f"(d1), "+f"(d2), "+f"(d3)
        : "r"(a0), "r"(a1), "r"(a2), "r"(a3), "r"(b0), "r"(b1));
}

__device__ __forceinline__ void ldsm_x4(uint32_t& r0, uint32_t& r1,
                                        uint32_t& r2, uint32_t& r3,
                                        const __nv_bfloat16* p)
{
    uint32_t addr = (uint32_t)__cvta_generic_to_shared(p);
    asm volatile("ldmatrix.sync.aligned.m8n8.x4.shared.b16 {%0,%1,%2,%3}, [%4];"
                 : "=r"(r0), "=r"(r1), "=r"(r2), "=r"(r3) : "r"(addr));
}

__device__ __forceinline__ void cp16(uint32_t smem_addr, const void* gptr)
{
    asm volatile("cp.async.cg.shared.global [%0], [%1], 16;"
                 :: "r"(smem_addr), "l"(gptr));
}

#define PITCH 40   // 32 + 8 bf16 pad

__global__ __launch_bounds__(256) void screen_kernel()
{
    __shared__ __align__(16) __nv_bfloat16 Abuf[2][128 * PITCH];
    __shared__ __align__(16) __nv_bfloat16 Bbuf[2][128 * PITCH];
    __shared__ float aS[128];
    __shared__ float bS[128];
    __shared__ unsigned rowminS[128];

    const int tid  = threadIdx.x;
    const int warp = tid >> 5;
    const int lane = tid & 31;
    const int wm   = warp >> 1;      // 0..3 -> 32 rows each
    const int wn   = warp & 1;       // 0..1 -> 64 cols each
    const int m0   = blockIdx.x * 128;
    const int j0   = blockIdx.y * 128;

    if (tid < 128) {
        aS[tid] = g_a[m0 + tid];
        bS[tid] = g_b[j0 + tid];
        rowminS[tid] = 0x7F800000u;
    }

    // per-thread prefetch coords: 512 x 16B segments per tile per chunk
    const int prow = tid >> 2;        // 0..63  (x2 via r-loop)
    const int pseg = tid & 3;         // 0..3 -> col seg*8 elements

    auto prefetch = [&](int buf, int k0) {
#pragma unroll
        for (int r = 0; r < 2; r++) {
            int row = prow + r * 64;
            uint32_t da = (uint32_t)__cvta_generic_to_shared(
                &Abuf[buf][row * PITCH + pseg * 8]);
            cp16(da, &g_Xh[(size_t)(m0 + row) * D_DIM + k0 + pseg * 8]);
            uint32_t db = (uint32_t)__cvta_generic_to_shared(
                &Bbuf[buf][row * PITCH + pseg * 8]);
            cp16(db, &g_Eh[(size_t)(j0 + row) * D_DIM + k0 + pseg * 8]);
        }
        asm volatile("cp.async.commit_group;");
    };

    float acc[2][8][4];
#pragma unroll
    for (int mt = 0; mt < 2; mt++)
#pragma unroll
        for (int nn = 0; nn < 8; nn++)
#pragma unroll
            for (int c = 0; c < 4; c++) acc[mt][nn][c] = 0.f;

    prefetch(0, 0);

    for (int c = 0; c < 8; c++) {            // 8 chunks of BK=32
        if (c < 7) prefetch((c + 1) & 1, (c + 1) * 32);
        if (c < 7) asm volatile("cp.async.wait_group 1;");
        else       asm volatile("cp.async.wait_group 0;");
        __syncthreads();

        const __nv_bfloat16* Asm = Abuf[c & 1];
        const __nv_bfloat16* Bsm = Bbuf[c & 1];
#pragma unroll
        for (int ks = 0; ks < 2; ks++) {
            const int krow = ks * 16;
            uint32_t a[2][4], b[4][4];
#pragma unroll
            for (int mt = 0; mt < 2; mt++) {
                const __nv_bfloat16* p =
                    &Asm[(wm * 32 + mt * 16 + (lane & 15)) * PITCH
                         + krow + (lane >> 4) * 8];
                ldsm_x4(a[mt][0], a[mt][1], a[mt][2], a[mt][3], p);
            }
#pragma unroll
            for (int nt = 0; nt < 4; nt++) {
                int nrow = wn * 64 + nt * 16 + (lane & 7) + ((lane >> 4) << 3);
                int kcol = krow + ((lane >> 3) & 1) * 8;
                ldsm_x4(b[nt][0], b[nt][1], b[nt][2], b[nt][3],
                        &Bsm[nrow * PITCH + kcol]);
            }
#pragma unroll
            for (int mt = 0; mt < 2; mt++)
#pragma unroll
                for (int nn = 0; nn < 8; nn++)
                    mma_bf16(acc[mt][nn][0], acc[mt][nn][1],
                             acc[mt][nn][2], acc[mt][nn][3],
                             a[mt][0], a[mt][1], a[mt][2], a[mt][3],
                             b[nn >> 1][(nn & 1) * 2], b[nn >> 1][(nn & 1) * 2 + 1]);
        }
        __syncthreads();
    }

    // epilogue: store s = b - 2*dot (fp16); track per-row approx-min of a+s
#pragma unroll
    for (int mt = 0; mt < 2; mt++) {
#pragma unroll
        for (int half = 0; half < 2; half++) {
            int lrow = wm * 32 + mt * 16 + half * 8 + (lane >> 2);
            int grow = m0 + lrow;
            float av = aS[lrow];
            float dmin = 3.4e38f;
#pragma unroll
            for (int nn = 0; nn < 8; nn++) {
                int lcol = wn * 64 + nn * 8 + (lane & 3) * 2;
                float s0 = bS[lcol]     - 2.f * acc[mt][nn][half * 2 + 0];
                float s1 = bS[lcol + 1] - 2.f * acc[mt][nn][half * 2 + 1];
                __half2 h = __floats2half2_rn(s0, s1);
                *reinterpret_cast<__half2*>(&g_Sh[(size_t)grow * K_CB + j0 + lcol]) = h;
                dmin = fminf(dmin, fminf(av + s0, av + s1));
            }
            dmin = fminf(dmin, __shfl_xor_sync(0xffffffffu, dmin, 1));
            dmin = fminf(dmin, __shfl_xor_sync(0xffffffffu, dmin, 2));
            if ((lane & 3) == 0)
                atomicMin(&rowminS[lrow], __float_as_uint(dmin));
        }
    }
    __syncthreads();
    if (tid < 128) atomicMin(&g_mina[m0 + tid], rowminS[tid]);
}

// ============================================================================
// Kernel 5: SELECT — scan fp16 s row, candidates within MARGIN of approx min,
// exact fp32 rescore (FROZEN semantics + smallest-index tie-break), write all
// outputs for the row (enc zeros fused).
// ============================================================================
__global__ __launch_bounds__(128) void select_kernel(
    const float* __restrict__ emb,
    float* __restrict__ quant, float* __restrict__ idxout,
    float* __restrict__ enc)
{
    __shared__ float uS[D_DIM];
    __shared__ int   cand[1024];
    __shared__ int   ncand;
    __shared__ unsigned long long best;
    __shared__ int   winner;

    const int m    = blockIdx.x;
    const int tid  = threadIdx.x;
    const int lane = tid & 31;
    const int warp = tid >> 5;

    if (tid == 0) { ncand = 0; best = 0ull; }
    {
        float2 v = *reinterpret_cast<const float2*>(&g_X[(size_t)m * D_DIM + tid * 2]);
        uS[tid * 2]     = v.x;
        uS[tid * 2 + 1] = v.y;
    }
    const float a   = g_a[m];
    const float thr = __uint_as_float(g_mina[m]) + MARGIN;
    __syncthreads();

    const __half* srow = &g_Sh[(size_t)m * K_CB];
    float* erow = &enc[(size_t)m * K_CB];
#pragma unroll
    for (int base = 0; base < K_CB; base += 512) {
        int idx = base + tid * 4;
        uint2 raw = *reinterpret_cast<const uint2*>(&srow[idx]);
        __half2 h01 = *reinterpret_cast<__half2*>(&raw.x);
        __half2 h23 = *reinterpret_cast<__half2*>(&raw.y);
        float2 s01 = __half22float2(h01);
        float2 s23 = __half22float2(h23);
        float d0 = a + s01.x, d1 = a + s01.y;
        float d2 = a + s23.x, d3 = a + s23.y;
        if (d0 <= thr) { int p = atomicAdd(&ncand, 1); if (p < 1024) cand[p] = idx; }
        if (d1 <= thr) { int p = atomicAdd(&ncand, 1); if (p < 1024) cand[p] = idx + 1; }
        if (d2 <= thr) { int p = atomicAdd(&ncand, 1); if (p < 1024) cand[p] = idx + 2; }
        if (d3 <= thr) { int p = atomicAdd(&ncand, 1); if (p < 1024) cand[p] = idx + 3; }
        *reinterpret_cast<float4*>(&erow[idx]) = make_float4(0.f, 0.f, 0.f, 0.f);
    }
    __syncthreads();

    const int nc = min(ncand, 1024);
    for (int ci = warp; ci < nc; ci += 4) {
        int k = cand[ci];
        const float* e = emb + (size_t)k * D_DIM;
        float4 u0 = *reinterpret_cast<const float4*>(&uS[lane * 8]);
        float4 u1 = *reinterpret_cast<const float4*>(&uS[lane * 8 + 4]);
        float4 e0 = *reinterpret_cast<const float4*>(&e[lane * 8]);
        float4 e1 = *reinterpret_cast<const float4*>(&e[lane * 8 + 4]);
        float dot = 0.f;
        dot = fmaf(u0.x, e0.x, dot); dot = fmaf(u0.y, e0.y, dot);
        dot = fmaf(u0.z, e0.z, dot); dot = fmaf(u0.w, e0.w, dot);
        dot = fmaf(u1.x, e1.x, dot); dot = fmaf(u1.y, e1.y, dot);
        dot = fmaf(u1.z, e1.z, dot); dot = fmaf(u1.w, e1.w, dot);
#pragma unroll
        for (int o = 16; o > 0; o >>= 1)
            dot = __fadd_rn(dot, __shfl_xor_sync(0xffffffffu, dot, o));
        if (lane == 0) {
            float c  = __fmul_rn(2.0f, dot);
            float dd = __fsub_rn(__fadd_rn(a, g_b[k]), c);
            unsigned u = __float_as_uint(dd);
            unsigned s = (u & 0x80000000u) ? ~u : (u | 0x80000000u);
            unsigned long long packed =
                ((unsigned long long)(~s) << 32) | (unsigned)(~(unsigned)k);
            atomicMax(&best, packed);
        }
    }
    __syncthreads();
    if (tid == 0) {
        int k = (int)(~(unsigned)(best & 0xffffffffull));
        winner = k;
        idxout[m] = (float)k;
        erow[k] = 1.0f;
    }
    __syncthreads();
    const int k = winner;
    if (tid < 64) {
        *reinterpret_cast<float4*>(&quant[(size_t)m * D_DIM + tid * 4]) =
            *reinterpret_cast<const float4*>(&emb[(size_t)k * D_DIM + tid * 4]);
    }
}

// ============================================================================
extern "C" void kernel_launch(void* const* d_in, const int* in_sizes, int n_in,
                              void* d_out, int out_size)
{
    const float* F     = (const float*)d_in[0];
    const float* Wp    = (const float*)d_in[1];
    const float* bp    = (const float*)d_in[2];
    const float* gamma = (const float*)d_in[3];
    const float* beta  = (const float*)d_in[4];
    const float* emb   = (const float*)d_in[5];

    float* out    = (float*)d_out;
    float* quant  = out;
    float* idxout = out + (size_t)N_ROWS * D_DIM;
    float* enc    = idxout + N_ROWS;

    proj_ln_kernel<<<N_ROWS / 64, 256>>>(F, Wp, bp, gamma, beta);
    eb_kernel<<<(K_CB * 32) / 256, 256>>>(emb);
    a_kernel<<<N_ROWS / 256, 256>>>();
    screen_kernel<<<dim3(N_ROWS / 128, K_CB / 128), 256>>>();
    select_kernel<<<N_ROWS, 128>>>(emb, quant, idxout, enc);
}

// round 8
// speedup vs baseline: 2.6709x; 1.0370x over previous
#include <cuda_runtime.h>
#include <cuda_bf16.h>
#include <cuda_fp16.h>
#include <cstdint>

#define N_ROWS 16384
#define H_DIM  512
#define D_DIM  256
#define K_CB   4096
#define MARGIN 2.5e-3f

// -------- scratch (static device arrays; no cudaMalloc allowed) --------
__device__ float          g_X [N_ROWS * D_DIM];     // post-LN activations (fp32)
__device__ __nv_bfloat16  g_Xh[N_ROWS * D_DIM];     // bf16 copy for screen
__device__ __nv_bfloat16  g_Eh[K_CB   * D_DIM];     // bf16 codebook
__device__ float          g_a [N_ROWS];             // fl(sum u^2) per row
__device__ float          g_b [K_CB];               // ||e_k||^2
__device__ unsigned       g_mina[N_ROWS];           // approx row-min d (float bits)
__device__ __half         g_Sh[(size_t)N_ROWS * K_CB]; // s = b - 2*dot (fp16)

// ============================================================================
// Kernel 1: projection GEMM + bias + LayerNorm (fused). NUMERICS FROZEN.
// ============================================================================
__global__ __launch_bounds__(256) void proj_ln_kernel(
    const float* __restrict__ F, const float* __restrict__ Wp,
    const float* __restrict__ bp, const float* __restrict__ gamma,
    const float* __restrict__ beta)
{
    __shared__ float As[32][68];
    __shared__ float Bs[32][260];

    const int tid  = threadIdx.x;
    const int warp = tid >> 5;
    const int lane = tid & 31;
    const int m0   = blockIdx.x * 64;

    float acc[8][8];
#pragma unroll
    for (int i = 0; i < 8; i++)
#pragma unroll
        for (int j = 0; j < 8; j++) acc[i][j] = 0.f;

    for (int k0 = 0; k0 < H_DIM; k0 += 32) {
#pragma unroll
        for (int r = 0; r < 2; r++) {
            int idx = tid + r * 256;
            int row = idx >> 3;
            int kk  = (idx & 7) * 4;
            float4 v = *reinterpret_cast<const float4*>(
                &F[(size_t)(m0 + row) * H_DIM + k0 + kk]);
            As[kk + 0][row] = v.x; As[kk + 1][row] = v.y;
            As[kk + 2][row] = v.z; As[kk + 3][row] = v.w;
        }
#pragma unroll
        for (int r = 0; r < 8; r++) {
            int idx = tid + r * 256;
            int d  = idx >> 3;
            int kk = (idx & 7) * 4;
            float4 v = *reinterpret_cast<const float4*>(
                &Wp[(size_t)d * H_DIM + k0 + kk]);
            Bs[kk + 0][d] = v.x; Bs[kk + 1][d] = v.y;
            Bs[kk + 2][d] = v.z; Bs[kk + 3][d] = v.w;
        }
        __syncthreads();
#pragma unroll
        for (int k = 0; k < 32; k++) {
            float4 a0 = *reinterpret_cast<const float4*>(&As[k][warp * 8]);
            float4 a1 = *reinterpret_cast<const float4*>(&As[k][warp * 8 + 4]);
            float4 b0 = *reinterpret_cast<const float4*>(&Bs[k][lane * 8]);
            float4 b1 = *reinterpret_cast<const float4*>(&Bs[k][lane * 8 + 4]);
            float a[8] = {a0.x, a0.y, a0.z, a0.w, a1.x, a1.y, a1.z, a1.w};
            float b[8] = {b0.x, b0.y, b0.z, b0.w, b1.x, b1.y, b1.z, b1.w};
#pragma unroll
            for (int i = 0; i < 8; i++)
#pragma unroll
                for (int j = 0; j < 8; j++) acc[i][j] = fmaf(a[i], b[j], acc[i][j]);
        }
        __syncthreads();
    }

    float bpv[8], gv[8], bv[8];
#pragma unroll
    for (int j = 0; j < 8; j++) {
        int d = lane * 8 + j;
        bpv[j] = bp[d]; gv[j] = gamma[d]; bv[j] = beta[d];
    }
#pragma unroll
    for (int i = 0; i < 8; i++) {
#pragma unroll
        for (int j = 0; j < 8; j++) acc[i][j] += bpv[j];
        float s = 0.f;
#pragma unroll
        for (int j = 0; j < 8; j++) s += acc[i][j];
#pragma unroll
        for (int o = 16; o > 0; o >>= 1) s += __shfl_xor_sync(0xffffffffu, s, o);
        float mu = s * (1.f / 256.f);
        float ss = 0.f;
#pragma unroll
        for (int j = 0; j < 8; j++) { float d2 = acc[i][j] - mu; ss += d2 * d2; }
#pragma unroll
        for (int o = 16; o > 0; o >>= 1) ss += __shfl_xor_sync(0xffffffffu, ss, o);
        float var = ss * (1.f / 256.f);
        float rs  = rsqrtf(var + 1e-5f);
        int row = m0 + warp * 8 + i;
        float out[8];
#pragma unroll
        for (int j = 0; j < 8; j++)
            out[j] = (acc[i][j] - mu) * rs * gv[j] + bv[j];
        *reinterpret_cast<float4*>(&g_X[(size_t)row * D_DIM + lane * 8]) =
            make_float4(out[0], out[1], out[2], out[3]);
        *reinterpret_cast<float4*>(&g_X[(size_t)row * D_DIM + lane * 8 + 4]) =
            make_float4(out[4], out[5], out[6], out[7]);
        __nv_bfloat162 h[4];
        h[0] = __floats2bfloat162_rn(out[0], out[1]);
        h[1] = __floats2bfloat162_rn(out[2], out[3]);
        h[2] = __floats2bfloat162_rn(out[4], out[5]);
        h[3] = __floats2bfloat162_rn(out[6], out[7]);
        *reinterpret_cast<uint4*>(&g_Xh[(size_t)row * D_DIM + lane * 8]) =
            *reinterpret_cast<uint4*>(h);
    }
}

// ============================================================================
// Kernel 2: per-code ||e||^2 + bf16 conversion.
// ============================================================================
__global__ __launch_bounds__(256) void eb_kernel(const float* __restrict__ emb)
{
    int k    = (blockIdx.x * blockDim.x + threadIdx.x) >> 5;
    int lane = threadIdx.x & 31;
    if (k >= K_CB) return;
    const float* row = emb + (size_t)k * D_DIM;
    float4 v0 = *reinterpret_cast<const float4*>(&row[lane * 8]);
    float4 v1 = *reinterpret_cast<const float4*>(&row[lane * 8 + 4]);
    float s = v0.x * v0.x + v0.y * v0.y + v0.z * v0.z + v0.w * v0.w
            + v1.x * v1.x + v1.y * v1.y + v1.z * v1.z + v1.w * v1.w;
#pragma unroll
    for (int o = 16; o > 0; o >>= 1) s += __shfl_xor_sync(0xffffffffu, s, o);
    if (lane == 0) g_b[k] = s;
    __nv_bfloat162 h[4];
    h[0] = __floats2bfloat162_rn(v0.x, v0.y);
    h[1] = __floats2bfloat162_rn(v0.z, v0.w);
    h[2] = __floats2bfloat162_rn(v1.x, v1.y);
    h[3] = __floats2bfloat162_rn(v1.z, v1.w);
    *reinterpret_cast<uint4*>(&g_Eh[(size_t)k * D_DIM + lane * 8]) =
        *reinterpret_cast<uint4*>(h);
}

// ============================================================================
// Kernel 3: g_a[m] (NUMERICS FROZEN); init g_mina.
// ============================================================================
__global__ __launch_bounds__(256) void a_kernel()
{
    int m = blockIdx.x * blockDim.x + threadIdx.x;
    if (m >= N_ROWS) return;
    const float* row = g_X + (size_t)m * D_DIM;
    float acc = 0.f;
#pragma unroll 8
    for (int d = 0; d < D_DIM; d++) {
        float v = row[d];
        acc = __fadd_rn(acc, __fmul_rn(v, v));
    }
    g_a[m] = acc;
    g_mina[m] = 0x7F800000u;   // +inf
}

// ============================================================================
// Kernel 4: SCREEN v5 — bf16 mma.sync + cp.async double buffer, ONE sync per
// chunk, enc zero-fill fused into the mainloop (this CTA's 128x128 enc block).
// BM=128, BN=128, BK=32, 8 warps, warp tile 32x64 (validated frag pattern).
// ============================================================================
__device__ __forceinline__ void mma_bf16(float& d0, float& d1, float& d2, float& d3,
                                         uint32_t a0, uint32_t a1, uint32_t a2, uint32_t a3,
                                         uint32_t b0, uint32_t b1)
{
    asm volatile(
        "mma.sync.aligned.m16n8k16.row.col.f32.bf16.bf16.f32 "
        "{%0,%1,%2,%3}, {%4,%5,%6,%7}, {%8,%9}, {%0,%1,%2,%3};"
        : "+f"(d0), "+f"(d1), "+f"(d2), "+f"(d3)
        : "r"(a0), "r"(a1), "r"(a2), "r"(a3), "r"(b0), "r"(b1));
}

__device__ __forceinline__ void ldsm_x4(uint32_t& r0, uint32_t& r1,
                                        uint32_t& r2, uint32_t& r3,
                                        const __nv_bfloat16* p)
{
    uint32_t addr = (uint32_t)__cvta_generic_to_shared(p);
    asm volatile("ldmatrix.sync.aligned.m8n8.x4.shared.b16 {%0,%1,%2,%3}, [%4];"
                 : "=r"(r0), "=r"(r1), "=r"(r2), "=r"(r3) : "r"(addr));
}

__device__ __forceinline__ void cp16(uint32_t smem_addr, const void* gptr)
{
    asm volatile("cp.async.cg.shared.global [%0], [%1], 16;"
                 :: "r"(smem_addr), "l"(gptr));
}

#define PITCH 40   // 32 + 8 bf16 pad

__global__ __launch_bounds__(256) void screen_kernel(float* __restrict__ enc)
{
    __shared__ __align__(16) __nv_bfloat16 Abuf[2][128 * PITCH];
    __shared__ __align__(16) __nv_bfloat16 Bbuf[2][128 * PITCH];
    __shared__ float aS[128];
    __shared__ float bS[128];
    __shared__ unsigned rowminS[128];

    const int tid  = threadIdx.x;
    const int warp = tid >> 5;
    const int lane = tid & 31;
    const int wm   = warp >> 1;      // 0..3 -> 32 rows each
    const int wn   = warp & 1;       // 0..1 -> 64 cols each
    const int m0   = blockIdx.x * 128;
    const int j0   = blockIdx.y * 128;

    if (tid < 128) {
        aS[tid] = g_a[m0 + tid];
        bS[tid] = g_b[j0 + tid];
        rowminS[tid] = 0x7F800000u;
    }

    const int prow = tid >> 2;        // 0..63
    const int pseg = tid & 3;         // 0..3

    auto prefetch = [&](int buf, int k0) {
#pragma unroll
        for (int r = 0; r < 2; r++) {
            int row = prow + r * 64;
            uint32_t da = (uint32_t)__cvta_generic_to_shared(
                &Abuf[buf][row * PITCH + pseg * 8]);
            cp16(da, &g_Xh[(size_t)(m0 + row) * D_DIM + k0 + pseg * 8]);
            uint32_t db = (uint32_t)__cvta_generic_to_shared(
                &Bbuf[buf][row * PITCH + pseg * 8]);
            cp16(db, &g_Eh[(size_t)(j0 + row) * D_DIM + k0 + pseg * 8]);
        }
        asm volatile("cp.async.commit_group;");
    };

    float acc[2][8][4];
#pragma unroll
    for (int mt = 0; mt < 2; mt++)
#pragma unroll
        for (int nn = 0; nn < 8; nn++)
#pragma unroll
            for (int c = 0; c < 4; c++) acc[mt][nn][c] = 0.f;

    const float4 z4 = make_float4(0.f, 0.f, 0.f, 0.f);

    prefetch(0, 0);

    for (int c = 0; c < 8; c++) {            // 8 chunks of BK=32
        asm volatile("cp.async.wait_group 0;");
        __syncthreads();
        if (c < 7) prefetch((c + 1) & 1, (c + 1) * 32);

        // fused enc zero-fill: 16 columns of this CTA's 128x128 block per chunk
#pragma unroll
        for (int r = 0; r < 2; r++) {
            int i   = tid + r * 256;          // 0..511
            int row = i >> 2;                 // 0..127
            int col = c * 16 + (i & 3) * 4;
            *reinterpret_cast<float4*>(
                &enc[(size_t)(m0 + row) * K_CB + j0 + col]) = z4;
        }

        const __nv_bfloat16* Asm = Abuf[c & 1];
        const __nv_bfloat16* Bsm = Bbuf[c & 1];
#pragma unroll
        for (int ks = 0; ks < 2; ks++) {
            const int krow = ks * 16;
            uint32_t a[2][4], b[4][4];
#pragma unroll
            for (int mt = 0; mt < 2; mt++) {
                const __nv_bfloat16* p =
                    &Asm[(wm * 32 + mt * 16 + (lane & 15)) * PITCH
                         + krow + (lane >> 4) * 8];
                ldsm_x4(a[mt][0], a[mt][1], a[mt][2], a[mt][3], p);
            }
#pragma unroll
            for (int nt = 0; nt < 4; nt++) {
                int nrow = wn * 64 + nt * 16 + (lane & 7) + ((lane >> 4) << 3);
                int kcol = krow + ((lane >> 3) & 1) * 8;
                ldsm_x4(b[nt][0], b[nt][1], b[nt][2], b[nt][3],
                        &Bsm[nrow * PITCH + kcol]);
            }
#pragma unroll
            for (int mt = 0; mt < 2; mt++)
#pragma unroll
                for (int nn = 0; nn < 8; nn++)
                    mma_bf16(acc[mt][nn][0], acc[mt][nn][1],
                             acc[mt][nn][2], acc[mt][nn][3],
                             a[mt][0], a[mt][1], a[mt][2], a[mt][3],
                             b[nn >> 1][(nn & 1) * 2], b[nn >> 1][(nn & 1) * 2 + 1]);
        }
    }

    // epilogue: store s = b - 2*dot (fp16); track per-row approx-min of a+s
#pragma unroll
    for (int mt = 0; mt < 2; mt++) {
#pragma unroll
        for (int half = 0; half < 2; half++) {
            int lrow = wm * 32 + mt * 16 + half * 8 + (lane >> 2);
            int grow = m0 + lrow;
            float av = aS[lrow];
            float dmin = 3.4e38f;
#pragma unroll
            for (int nn = 0; nn < 8; nn++) {
                int lcol = wn * 64 + nn * 8 + (lane & 3) * 2;
                float s0 = bS[lcol]     - 2.f * acc[mt][nn][half * 2 + 0];
                float s1 = bS[lcol + 1] - 2.f * acc[mt][nn][half * 2 + 1];
                __half2 h = __floats2half2_rn(s0, s1);
                *reinterpret_cast<__half2*>(&g_Sh[(size_t)grow * K_CB + j0 + lcol]) = h;
                dmin = fminf(dmin, fminf(av + s0, av + s1));
            }
            dmin = fminf(dmin, __shfl_xor_sync(0xffffffffu, dmin, 1));
            dmin = fminf(dmin, __shfl_xor_sync(0xffffffffu, dmin, 2));
            if ((lane & 3) == 0)
                atomicMin(&rowminS[lrow], __float_as_uint(dmin));
        }
    }
    __syncthreads();
    if (tid < 128) atomicMin(&g_mina[m0 + tid], rowminS[tid]);
}

// ============================================================================
// Kernel 5: SELECT — scan fp16 s row, candidates within MARGIN of approx min,
// exact fp32 rescore (FROZEN semantics + smallest-index tie-break).
// enc zeros now written by screen; only the 1.0 scatter remains here.
// ============================================================================
__global__ __launch_bounds__(128) void select_kernel(
    const float* __restrict__ emb,
    float* __restrict__ quant, float* __restrict__ idxout,
    float* __restrict__ enc)
{
    __shared__ float uS[D_DIM];
    __shared__ int   cand[1024];
    __shared__ int   ncand;
    __shared__ unsigned long long best;
    __shared__ int   winner;

    const int m    = blockIdx.x;
    const int tid  = threadIdx.x;
    const int lane = tid & 31;
    const int warp = tid >> 5;

    if (tid == 0) { ncand = 0; best = 0ull; }
    {
        float2 v = *reinterpret_cast<const float2*>(&g_X[(size_t)m * D_DIM + tid * 2]);
        uS[tid * 2]     = v.x;
        uS[tid * 2 + 1] = v.y;
    }
    const float a   = g_a[m];
    const float thr = __uint_as_float(g_mina[m]) + MARGIN;
    __syncthreads();

    const __half* srow = &g_Sh[(size_t)m * K_CB];
#pragma unroll
    for (int base = 0; base < K_CB; base += 1024) {
        int idx = base + tid * 8;
        uint4 raw = *reinterpret_cast<const uint4*>(&srow[idx]);
        const uint32_t rw[4] = {raw.x, raw.y, raw.z, raw.w};
#pragma unroll
        for (int q = 0; q < 4; q++) {
            __half2 h = *reinterpret_cast<const __half2*>(&rw[q]);
            float2 s2 = __half22float2(h);
            float d0 = a + s2.x, d1 = a + s2.y;
            if (d0 <= thr) { int p = atomicAdd(&ncand, 1); if (p < 1024) cand[p] = idx + q * 2; }
            if (d1 <= thr) { int p = atomicAdd(&ncand, 1); if (p < 1024) cand[p] = idx + q * 2 + 1; }
        }
    }
    __syncthreads();

    const int nc = min(ncand, 1024);
    for (int ci = warp; ci < nc; ci += 4) {
        int k = cand[ci];
        const float* e = emb + (size_t)k * D_DIM;
        float4 u0 = *reinterpret_cast<const float4*>(&uS[lane * 8]);
        float4 u1 = *reinterpret_cast<const float4*>(&uS[lane * 8 + 4]);
        float4 e0 = *reinterpret_cast<const float4*>(&e[lane * 8]);
        float4 e1 = *reinterpret_cast<const float4*>(&e[lane * 8 + 4]);
        float dot = 0.f;
        dot = fmaf(u0.x, e0.x, dot); dot = fmaf(u0.y, e0.y, dot);
        dot = fmaf(u0.z, e0.z, dot); dot = fmaf(u0.w, e0.w, dot);
        dot = fmaf(u1.x, e1.x, dot); dot = fmaf(u1.y, e1.y, dot);
        dot = fmaf(u1.z, e1.z, dot); dot = fmaf(u1.w, e1.w, dot);
#pragma unroll
        for (int o = 16; o > 0; o >>= 1)
            dot = __fadd_rn(dot, __shfl_xor_sync(0xffffffffu, dot, o));
        if (lane == 0) {
            float c  = __fmul_rn(2.0f, dot);
            float dd = __fsub_rn(__fadd_rn(a, g_b[k]), c);
            unsigned u = __float_as_uint(dd);
            unsigned s = (u & 0x80000000u) ? ~u : (u | 0x80000000u);
            unsigned long long packed =
                ((unsigned long long)(~s) << 32) | (unsigned)(~(unsigned)k);
            atomicMax(&best, packed);
        }
    }
    __syncthreads();
    if (tid == 0) {
        int k = (int)(~(unsigned)(best & 0xffffffffull));
        winner = k;
        idxout[m] = (float)k;
        enc[(size_t)m * K_CB + k] = 1.0f;
    }
    __syncthreads();
    const int k = winner;
    if (tid < 64) {
        *reinterpret_cast<float4*>(&quant[(size_t)m * D_DIM + tid * 4]) =
            *reinterpret_cast<const float4*>(&emb[(size_t)k * D_DIM + tid * 4]);
    }
}

// ============================================================================
extern "C" void kernel_launch(void* const* d_in, const int* in_sizes, int n_in,
                              void* d_out, int out_size)
{
    const float* F     = (const float*)d_in[0];
    const float* Wp    = (const float*)d_in[1];
    const float* bp    = (const float*)d_in[2];
    const float* gamma = (const float*)d_in[3];
    const float* beta  = (const float*)d_in[4];
    const float* emb   = (const float*)d_in[5];

    float* out    = (float*)d_out;
    float* quant  = out;
    float* idxout = out + (size_t)N_ROWS * D_DIM;
    float* enc    = idxout + N_ROWS;

    proj_ln_kernel<<<N_ROWS / 64, 256>>>(F, Wp, bp, gamma, beta);
    eb_kernel<<<(K_CB * 32) / 256, 256>>>(emb);
    a_kernel<<<N_ROWS / 256, 256>>>();
    screen_kernel<<<dim3(N_ROWS / 128, K_CB / 128), 256>>>(enc);
    select_kernel<<<N_ROWS, 128>>>(emb, quant, idxout, enc);
}